// round 1
// baseline (speedup 1.0000x reference)
#include <cuda_runtime.h>

// CausalGRNEMA: ema scan along T (alpha=0.99) + per-(b,t) channel mean + fused output.
// Strategy: chunked scan with decayed warmup window (alpha^1024 ~ 3.4e-5 -> exact enough),
// 128 blocks co-resident, warmup reads alias the previous chunk's main reads for L2 reuse.

#define ALPHA   0.99f
#define OMA     0.01f
#define EPSF    1e-6f
#define EMAINIT 1e-4f

static constexpr int B = 16;
static constexpr int T = 8192;
static constexpr int C = 512;
static constexpr int L = 1024;           // output chunk per block
static constexpr int W = 1024;           // warmup window (== L: aliases prev chunk)
static constexpr int CHUNKS = T / L;     // 8
static constexpr int U = 8;              // timesteps per batch
static constexpr int NTHREADS = C;       // 1 thread per channel
static constexpr int NWARPS = NTHREADS / 32;  // 16

// per-t constants: tab[t] = (EPS*D_t, 1/sqrt(D_t)) with D_t = (1 - alpha^(t+1)) + EPS
__device__ float2 g_tab[T];

__global__ void tab_kernel() {
    int t = blockIdx.x * blockDim.x + threadIdx.x;
    if (t < T) {
        double D = 1.0 - exp((double)(t + 1) * log(0.99)) + 1e-6;
        g_tab[t] = make_float2((float)(1e-6 * D), (float)(1.0 / sqrt(D)));
    }
}

__global__ __launch_bounds__(NTHREADS, 1)
void grnema_kernel(const float* __restrict__ x,
                   const float* __restrict__ gamma,
                   const float* __restrict__ beta,
                   float* __restrict__ y) {
    const int b = blockIdx.x / CHUNKS;
    const int k = blockIdx.x % CHUNKS;
    const int c = threadIdx.x;
    const int lane = c & 31;
    const int wid  = c >> 5;

    __shared__ float red[U][NWARPS];
    __shared__ float inv[U];

    const float gm = gamma[c];
    const float bt = beta[c];

    const float* __restrict__ xb = x + (size_t)b * T * C + c;
    float* __restrict__ yb       = y + (size_t)b * T * C + c;

    float ema;
    int t0;
    if (k == 0) { ema = EMAINIT; t0 = 0; }
    else        { ema = 0.0f;    t0 = k * L - W; }
    const int tmain = k * L;

    // ---- warmup: scan only, 16-deep load batches for MLP ----
    for (int t = t0; t < tmain; t += 16) {
        float xv[16];
        #pragma unroll
        for (int u = 0; u < 16; u++) xv[u] = xb[(size_t)(t + u) * C];
        #pragma unroll
        for (int u = 0; u < 16; u++) ema = fmaf(ALPHA, ema, OMA * xv[u] * xv[u]);
    }

    // ---- main: software-pipelined batches of U timesteps ----
    float xv[U];
    #pragma unroll
    for (int u = 0; u < U; u++) xv[u] = xb[(size_t)(tmain + u) * C];

    for (int t = tmain; t < tmain + L; t += U) {
        // prefetch next batch
        float xn[U];
        if (t + U < tmain + L) {
            #pragma unroll
            for (int u = 0; u < U; u++) xn[u] = xb[(size_t)(t + U + u) * C];
        }

        // per-t constants (uniform broadcast loads, L1-resident)
        float2 cs[U];
        #pragma unroll
        for (int u = 0; u < U; u++) cs[u] = g_tab[t + u];

        // scan + g
        float g[U];
        #pragma unroll
        for (int u = 0; u < U; u++) {
            ema = fmaf(ALPHA, ema, OMA * xv[u] * xv[u]);
            g[u] = sqrtf(ema + cs[u].x) * cs[u].y;
        }

        // warp-level reduce for each u (independent chains pipeline)
        #pragma unroll
        for (int u = 0; u < U; u++) {
            float s = g[u];
            s += __shfl_xor_sync(0xffffffffu, s, 16);
            s += __shfl_xor_sync(0xffffffffu, s, 8);
            s += __shfl_xor_sync(0xffffffffu, s, 4);
            s += __shfl_xor_sync(0xffffffffu, s, 2);
            s += __shfl_xor_sync(0xffffffffu, s, 1);
            if (lane == 0) red[u][wid] = s;
        }
        __syncthreads();

        // warps 0..U-1: reduce 16 partials for timestep u = wid, publish 1/(mean+eps)
        if (wid < U && lane < NWARPS) {
            float s = red[wid][lane];
            s += __shfl_xor_sync(0x0000ffffu, s, 8);
            s += __shfl_xor_sync(0x0000ffffu, s, 4);
            s += __shfl_xor_sync(0x0000ffffu, s, 2);
            s += __shfl_xor_sync(0x0000ffffu, s, 1);
            if (lane == 0) inv[wid] = __fdividef(1.0f, s * (1.0f / C) + EPSF);
        }
        __syncthreads();

        // epilogue: y = gamma*(x*n) + beta + x
        #pragma unroll
        for (int u = 0; u < U; u++) {
            float n = g[u] * inv[u];
            yb[(size_t)(t + u) * C] = fmaf(gm, xv[u] * n, xv[u] + bt);
        }

        #pragma unroll
        for (int u = 0; u < U; u++) xv[u] = xn[u];
    }
}

extern "C" void kernel_launch(void* const* d_in, const int* in_sizes, int n_in,
                              void* d_out, int out_size) {
    const float* x     = (const float*)d_in[0];
    const float* gamma = (const float*)d_in[1];
    const float* beta  = (const float*)d_in[2];
    float* y           = (float*)d_out;

    tab_kernel<<<(T + 255) / 256, 256>>>();
    grnema_kernel<<<B * CHUNKS, NTHREADS>>>(x, gamma, beta, y);
}

// round 2
// speedup vs baseline: 1.1987x; 1.1987x over previous
#include <cuda_runtime.h>

// CausalGRNEMA: ema scan along T (alpha=0.99) + per-(b,t) channel mean + fused output.
// R2: L=512/W=512 -> 256 blocks (2/SM, occ 50%), double-buffered single-barrier
// reduction (warps redundantly reduce partials -> no 2nd sync / broadcast).

#define ALPHA   0.99f
#define OMA     0.01f
#define EPSF    1e-6f
#define EMAINIT 1e-4f

static constexpr int B = 16;
static constexpr int T = 8192;
static constexpr int C = 512;
static constexpr int L = 512;            // output chunk per block
static constexpr int W = 512;            // warmup window (alpha^512 ~ 5.9e-3 -> y err ~5e-5)
static constexpr int CHUNKS = T / L;     // 16
static constexpr int U = 8;              // timesteps per batch
static constexpr int NTHREADS = C;       // 1 thread per channel
static constexpr int NWARPS = NTHREADS / 32;  // 16

// per-t constants: tab[t] = (EPS*D_t, 1/sqrt(D_t)) with D_t = (1 - alpha^(t+1)) + EPS
__device__ float2 g_tab[T];

__global__ void tab_kernel() {
    int t = blockIdx.x * blockDim.x + threadIdx.x;
    if (t < T) {
        double D = 1.0 - exp((double)(t + 1) * log(0.99)) + 1e-6;
        g_tab[t] = make_float2((float)(1e-6 * D), (float)(1.0 / sqrt(D)));
    }
}

__global__ __launch_bounds__(NTHREADS, 2)
void grnema_kernel(const float* __restrict__ x,
                   const float* __restrict__ gamma,
                   const float* __restrict__ beta,
                   float* __restrict__ y) {
    const int b = blockIdx.x / CHUNKS;
    const int k = blockIdx.x % CHUNKS;
    const int c = threadIdx.x;
    const int lane = c & 31;
    const int wid  = c >> 5;

    __shared__ float red[2][U][NWARPS];   // double-buffered warp partials

    const float gm = gamma[c];
    const float bt = beta[c];

    const float* __restrict__ xb = x + (size_t)b * T * C + c;
    float* __restrict__ yb       = y + (size_t)b * T * C + c;

    float ema;
    int t0;
    if (k == 0) { ema = EMAINIT; t0 = 0; }
    else        { ema = 0.0f;    t0 = k * L - W; }
    const int tmain = k * L;

    // ---- warmup: scan only, 16-deep load batches for MLP ----
    for (int t = t0; t < tmain; t += 16) {
        float xv[16];
        #pragma unroll
        for (int u = 0; u < 16; u++) xv[u] = xb[(size_t)(t + u) * C];
        #pragma unroll
        for (int u = 0; u < 16; u++) ema = fmaf(ALPHA, ema, OMA * xv[u] * xv[u]);
    }

    // ---- main: software-pipelined batches of U timesteps, 1 barrier per batch ----
    float xv[U];
    #pragma unroll
    for (int u = 0; u < U; u++) xv[u] = xb[(size_t)(tmain + u) * C];

    int parity = 0;
    for (int t = tmain; t < tmain + L; t += U, parity ^= 1) {
        // prefetch next batch
        float xn[U];
        if (t + U < tmain + L) {
            #pragma unroll
            for (int u = 0; u < U; u++) xn[u] = xb[(size_t)(t + U + u) * C];
        }

        // per-t constants (uniform broadcast loads, L1-resident)
        float2 cs[U];
        #pragma unroll
        for (int u = 0; u < U; u++) cs[u] = g_tab[t + u];

        // scan + g
        float g[U];
        #pragma unroll
        for (int u = 0; u < U; u++) {
            ema = fmaf(ALPHA, ema, OMA * xv[u] * xv[u]);
            g[u] = sqrtf(ema + cs[u].x) * cs[u].y;
        }

        // warp-level reduce for each u
        #pragma unroll
        for (int u = 0; u < U; u++) {
            float s = g[u];
            s += __shfl_xor_sync(0xffffffffu, s, 16);
            s += __shfl_xor_sync(0xffffffffu, s, 8);
            s += __shfl_xor_sync(0xffffffffu, s, 4);
            s += __shfl_xor_sync(0xffffffffu, s, 2);
            s += __shfl_xor_sync(0xffffffffu, s, 1);
            if (lane == 0) red[parity][u][wid] = s;
        }
        __syncthreads();

        // every warp redundantly reduces the 16 partials for all U timesteps
        // (no second barrier; next iteration writes the other buffer)
        float inv[U];
        #pragma unroll
        for (int u = 0; u < U; u++) {
            float s = red[parity][u][lane & 15];
            s += __shfl_xor_sync(0xffffffffu, s, 8);
            s += __shfl_xor_sync(0xffffffffu, s, 4);
            s += __shfl_xor_sync(0xffffffffu, s, 2);
            s += __shfl_xor_sync(0xffffffffu, s, 1);
            inv[u] = __fdividef(1.0f, s * (1.0f / C) + EPSF);
        }

        // epilogue: y = gamma*(x*n) + beta + x
        #pragma unroll
        for (int u = 0; u < U; u++) {
            float n = g[u] * inv[u];
            yb[(size_t)(t + u) * C] = fmaf(gm, xv[u] * n, xv[u] + bt);
        }

        #pragma unroll
        for (int u = 0; u < U; u++) xv[u] = xn[u];
    }
}

extern "C" void kernel_launch(void* const* d_in, const int* in_sizes, int n_in,
                              void* d_out, int out_size) {
    const float* x     = (const float*)d_in[0];
    const float* gamma = (const float*)d_in[1];
    const float* beta  = (const float*)d_in[2];
    float* y           = (float*)d_out;

    tab_kernel<<<(T + 255) / 256, 256>>>();
    grnema_kernel<<<B * CHUNKS, NTHREADS>>>(x, gamma, beta, y);
}

// round 3
// speedup vs baseline: 1.3261x; 1.1063x over previous
#include <cuda_runtime.h>
#include <math.h>

// CausalGRNEMA exact chunked scan, 3 passes:
//  pass1: per-chunk local ema aggregate S_k (state 0 start)
//  pass2: sequential combine -> exact carry-in E_{k-1} per chunk
//  pass3: rescan chunk with carry-in, channel-mean, fused epilogue
// L=128 -> 1024 independent blocks in passes 1/3, zero read amplification.

#define ALPHA   0.99f
#define OMA     0.01f
#define EPSF    1e-6f
#define EMAINIT 1e-4f

static constexpr int B = 16;
static constexpr int T = 8192;
static constexpr int C = 512;
static constexpr int C4 = C / 4;          // 128 float4 lanes
static constexpr int L = 128;             // chunk length
static constexpr int NCHUNK = T / L;      // 64
static constexpr int NT = 128;            // threads (1 float4 per thread)
static constexpr int U = 4;               // timesteps per batch in pass3

__device__ float2 g_tab[T];               // (EPS*D_t, 1/sqrt(D_t)), D_t = 1-alpha^(t+1)+EPS
__device__ float  g_S[B * NCHUNK * C];    // chunk aggregates
__device__ float  g_Ein[B * NCHUNK * C];  // exact carry-in per chunk

__global__ void tab_kernel() {
    int t = blockIdx.x * blockDim.x + threadIdx.x;
    if (t < T) {
        double D = 1.0 - exp((double)(t + 1) * log(0.99)) + 1e-6;
        g_tab[t] = make_float2((float)(1e-6 * D), (float)(1.0 / sqrt(D)));
    }
}

// ---- pass1: local scan, aggregate only ----
__global__ __launch_bounds__(NT, 6)
void pass1_kernel(const float* __restrict__ x) {
    const int b = blockIdx.x / NCHUNK;
    const int k = blockIdx.x % NCHUNK;
    const int c4 = threadIdx.x;

    const float4* __restrict__ xb =
        (const float4*)x + ((size_t)b * T + (size_t)k * L) * C4 + c4;

    float4 e = make_float4(0.f, 0.f, 0.f, 0.f);
    float4 cur[8], nxt[8];
    #pragma unroll
    for (int u = 0; u < 8; u++) cur[u] = xb[(size_t)u * C4];

    for (int t = 0; t < L; t += 8) {
        if (t + 8 < L) {
            #pragma unroll
            for (int u = 0; u < 8; u++) nxt[u] = xb[(size_t)(t + 8 + u) * C4];
        }
        #pragma unroll
        for (int u = 0; u < 8; u++) {
            e.x = fmaf(ALPHA, e.x, OMA * cur[u].x * cur[u].x);
            e.y = fmaf(ALPHA, e.y, OMA * cur[u].y * cur[u].y);
            e.z = fmaf(ALPHA, e.z, OMA * cur[u].z * cur[u].z);
            e.w = fmaf(ALPHA, e.w, OMA * cur[u].w * cur[u].w);
        }
        #pragma unroll
        for (int u = 0; u < 8; u++) cur[u] = nxt[u];
    }
    ((float4*)g_S)[((size_t)b * NCHUNK + k) * C4 + c4] = e;
}

// ---- pass2: exact carry combine across chunks ----
__global__ void pass2_kernel() {
    const int idx = blockIdx.x * blockDim.x + threadIdx.x;  // b*C + c
    if (idx >= B * C) return;
    const int b = idx / C;
    const int c = idx % C;
    const float aL = (float)exp((double)L * log(0.99));
    float E = EMAINIT;
    #pragma unroll 8
    for (int k = 0; k < NCHUNK; k++) {
        const size_t o = ((size_t)b * NCHUNK + k) * C + c;
        g_Ein[o] = E;
        E = fmaf(aL, E, g_S[o]);
    }
}

// ---- pass3: rescan with exact carry-in, mean over C, fused epilogue ----
__global__ __launch_bounds__(NT, 6)
void pass3_kernel(const float* __restrict__ x,
                  const float* __restrict__ gamma,
                  const float* __restrict__ beta,
                  float* __restrict__ y) {
    // reverse order: read the L2-hot tail of pass1 first
    const int item = (B * NCHUNK - 1) - blockIdx.x;
    const int b = item / NCHUNK;
    const int k = item % NCHUNK;
    const int c4 = threadIdx.x;
    const int lane = threadIdx.x & 31;
    const int wid  = threadIdx.x >> 5;

    __shared__ __align__(16) float red[2][U][4];   // [parity][u][warp]

    const float4 gm = ((const float4*)gamma)[c4];
    const float4 bt = ((const float4*)beta)[c4];

    const float4* __restrict__ xb =
        (const float4*)x + ((size_t)b * T + (size_t)k * L) * C4 + c4;
    float4* __restrict__ yb =
        (float4*)y + ((size_t)b * T + (size_t)k * L) * C4 + c4;

    float4 ema = ((const float4*)g_Ein)[((size_t)b * NCHUNK + k) * C4 + c4];

    float4 cur[U], nxt[U];
    #pragma unroll
    for (int u = 0; u < U; u++) cur[u] = xb[(size_t)u * C4];

    int par = 0;
    for (int t = 0; t < L; t += U, par ^= 1) {
        if (t + U < L) {
            #pragma unroll
            for (int u = 0; u < U; u++) nxt[u] = xb[(size_t)(t + U + u) * C4];
        }

        float2 cs[U];
        #pragma unroll
        for (int u = 0; u < U; u++) cs[u] = g_tab[k * L + t + u];

        float4 g[U];
        #pragma unroll
        for (int u = 0; u < U; u++) {
            ema.x = fmaf(ALPHA, ema.x, OMA * cur[u].x * cur[u].x);
            ema.y = fmaf(ALPHA, ema.y, OMA * cur[u].y * cur[u].y);
            ema.z = fmaf(ALPHA, ema.z, OMA * cur[u].z * cur[u].z);
            ema.w = fmaf(ALPHA, ema.w, OMA * cur[u].w * cur[u].w);
            float vx = ema.x + cs[u].x, vy = ema.y + cs[u].x;
            float vz = ema.z + cs[u].x, vw = ema.w + cs[u].x;
            g[u].x = __frsqrt_rn(vx) * vx * cs[u].y;
            g[u].y = __frsqrt_rn(vy) * vy * cs[u].y;
            g[u].z = __frsqrt_rn(vz) * vz * cs[u].y;
            g[u].w = __frsqrt_rn(vw) * vw * cs[u].y;

            float s = (g[u].x + g[u].y) + (g[u].z + g[u].w);
            s += __shfl_xor_sync(0xffffffffu, s, 16);
            s += __shfl_xor_sync(0xffffffffu, s, 8);
            s += __shfl_xor_sync(0xffffffffu, s, 4);
            s += __shfl_xor_sync(0xffffffffu, s, 2);
            s += __shfl_xor_sync(0xffffffffu, s, 1);
            if (lane == 0) red[par][u][wid] = s;
        }
        __syncthreads();

        #pragma unroll
        for (int u = 0; u < U; u++) {
            float4 r = *(const float4*)&red[par][u][0];
            float tot = (r.x + r.y) + (r.z + r.w);
            float inv = __fdividef(1.0f, tot * (1.0f / C) + EPSF);
            float4 o;
            float nx = g[u].x * inv, ny = g[u].y * inv;
            float nz = g[u].z * inv, nw = g[u].w * inv;
            o.x = fmaf(gm.x, cur[u].x * nx, cur[u].x + bt.x);
            o.y = fmaf(gm.y, cur[u].y * ny, cur[u].y + bt.y);
            o.z = fmaf(gm.z, cur[u].z * nz, cur[u].z + bt.z);
            o.w = fmaf(gm.w, cur[u].w * nw, cur[u].w + bt.w);
            yb[(size_t)(t + u) * C4] = o;
        }

        #pragma unroll
        for (int u = 0; u < U; u++) cur[u] = nxt[u];
    }
}

extern "C" void kernel_launch(void* const* d_in, const int* in_sizes, int n_in,
                              void* d_out, int out_size) {
    const float* x     = (const float*)d_in[0];
    const float* gamma = (const float*)d_in[1];
    const float* beta  = (const float*)d_in[2];
    float* y           = (float*)d_out;

    tab_kernel<<<(T + 255) / 256, 256>>>();
    pass1_kernel<<<B * NCHUNK, NT>>>(x);
    pass2_kernel<<<(B * C + 127) / 128, 128>>>();
    pass3_kernel<<<B * NCHUNK, NT>>>(x, gamma, beta, y);
}

// round 4
// speedup vs baseline: 1.5209x; 1.1469x over previous
#include <cuda_runtime.h>
#include <math.h>

// CausalGRNEMA exact chunked scan, warp-autonomous:
//  pass1: per-(b,chunk) warp scans 64 timesteps from state 0 -> aggregate S (f-units)
//  pass2: serial combine over 128 chunks -> exact carry-in per chunk (+ builds g_tab)
//  pass3: per-(b,chunk) warp rescans with carry-in; channel mean is warp-internal
//         (16 ch/lane, 5 shfl) -> no __syncthreads, no inter-warp coupling.
// State kept scaled: f = ema/OMA, f' = alpha*f + x^2 (2 instr/elem).

#define ALPHA   0.99f
#define OMA     0.01f
#define EPSF    1e-6f
#define EMAINIT 1e-4f

static constexpr int B  = 16;
static constexpr int T  = 8192;
static constexpr int C  = 512;
static constexpr int C4 = C / 4;          // 128 float4 columns
static constexpr int LC = 64;             // timesteps per warp task
static constexpr int NCH = T / LC;        // 128 chunks
static constexpr int WPB = 8;             // warps per block
static constexpr int NTASK = B * NCH;     // 2048 warp tasks

__device__ float2 g_tab[T];               // (EPS*D_t, EPS*sqrt(D_t)), D_t = 1-alpha^(t+1)+EPS
__device__ float  g_S[NTASK * C];         // chunk aggregates (f-units)
__device__ float  g_Ein[NTASK * C];       // exact carry-in per chunk (f-units)

// ---- pass1: warp-autonomous local scan, aggregate only ----
__global__ __launch_bounds__(256, 3)
void pass1_kernel(const float* __restrict__ x) {
    const int warp = threadIdx.x >> 5;
    const int lane = threadIdx.x & 31;
    const int task = blockIdx.x * WPB + warp;
    const int b = task >> 7;              // /NCH
    const int k = task & (NCH - 1);

    const float4* __restrict__ xb =
        (const float4*)x + ((size_t)b * T + (size_t)k * LC) * C4;

    float4 f[4], cur[4], nxt[4];
    #pragma unroll
    for (int j = 0; j < 4; j++) f[j] = make_float4(0.f, 0.f, 0.f, 0.f);
    #pragma unroll
    for (int j = 0; j < 4; j++) cur[j] = xb[lane + j * 32];

    for (int t = 0; t < LC; t++) {
        if (t + 1 < LC) {
            #pragma unroll
            for (int j = 0; j < 4; j++) nxt[j] = xb[(size_t)(t + 1) * C4 + lane + j * 32];
        }
        #pragma unroll
        for (int j = 0; j < 4; j++) {
            f[j].x = fmaf(ALPHA, f[j].x, cur[j].x * cur[j].x);
            f[j].y = fmaf(ALPHA, f[j].y, cur[j].y * cur[j].y);
            f[j].z = fmaf(ALPHA, f[j].z, cur[j].z * cur[j].z);
            f[j].w = fmaf(ALPHA, f[j].w, cur[j].w * cur[j].w);
        }
        #pragma unroll
        for (int j = 0; j < 4; j++) cur[j] = nxt[j];
    }
    float4* __restrict__ S4 = (float4*)g_S + (size_t)task * C4;
    #pragma unroll
    for (int j = 0; j < 4; j++) S4[lane + j * 32] = f[j];
}

// ---- pass2: build g_tab + exact carry combine across chunks ----
__global__ void pass2_kernel() {
    const int idx = blockIdx.x * blockDim.x + threadIdx.x;  // 0..B*C-1 (== T)
    if (idx < T) {
        double D = 1.0 - exp((double)(idx + 1) * log(0.99)) + 1e-6;
        g_tab[idx] = make_float2((float)(1e-6 * D), (float)(1e-6 * sqrt(D)));
    }
    if (idx >= B * C) return;
    const int b = idx / C;
    const int c = idx % C;
    const float aL = (float)exp((double)LC * log(0.99));
    float E = EMAINIT / OMA;              // f-units
    #pragma unroll 8
    for (int k = 0; k < NCH; k++) {
        const size_t o = ((size_t)b * NCH + k) * C + c;
        g_Ein[o] = E;
        E = fmaf(aL, E, g_S[o]);
    }
}

// ---- pass3: warp-autonomous rescan + warp-internal channel mean + epilogue ----
__global__ __launch_bounds__(256, 2)
void pass3_kernel(const float* __restrict__ x,
                  const float* __restrict__ gamma,
                  const float* __restrict__ beta,
                  float* __restrict__ y) {
    __shared__ float4 sg[C4], sb[C4];
    {
        const int tid = threadIdx.x;
        if (tid < C4)       sg[tid]      = ((const float4*)gamma)[tid];
        else                sb[tid - C4] = ((const float4*)beta)[tid - C4];
    }
    __syncthreads();   // once

    const int warp = threadIdx.x >> 5;
    const int lane = threadIdx.x & 31;
    const int task = blockIdx.x * WPB + warp;
    const int b = task >> 7;
    const int k = task & (NCH - 1);
    const int tbase = k * LC;

    const float4* __restrict__ xb =
        (const float4*)x + ((size_t)b * T + tbase) * C4;
    float4* __restrict__ yb =
        (float4*)y + ((size_t)b * T + tbase) * C4;

    float4 f[4];
    {
        const float4* __restrict__ E4 = (const float4*)g_Ein + (size_t)task * C4;
        #pragma unroll
        for (int j = 0; j < 4; j++) f[j] = E4[lane + j * 32];
    }

    float4 cur[4], nxt[4];
    #pragma unroll
    for (int j = 0; j < 4; j++) cur[j] = xb[lane + j * 32];

    for (int t = 0; t < LC; t++) {
        if (t + 1 < LC) {
            #pragma unroll
            for (int j = 0; j < 4; j++) nxt[j] = xb[(size_t)(t + 1) * C4 + lane + j * 32];
        }
        const float2 cs = g_tab[tbase + t];   // (EPS*D, EPS*sqrt(D))

        float4 s[4];
        float acc = 0.0f;
        #pragma unroll
        for (int j = 0; j < 4; j++) {
            f[j].x = fmaf(ALPHA, f[j].x, cur[j].x * cur[j].x);
            f[j].y = fmaf(ALPHA, f[j].y, cur[j].y * cur[j].y);
            f[j].z = fmaf(ALPHA, f[j].z, cur[j].z * cur[j].z);
            f[j].w = fmaf(ALPHA, f[j].w, cur[j].w * cur[j].w);
            float vx = fmaf(OMA, f[j].x, cs.x);
            float vy = fmaf(OMA, f[j].y, cs.x);
            float vz = fmaf(OMA, f[j].z, cs.x);
            float vw = fmaf(OMA, f[j].w, cs.x);
            s[j].x = __frsqrt_rn(vx) * vx;    // = sqrt(vx)
            s[j].y = __frsqrt_rn(vy) * vy;
            s[j].z = __frsqrt_rn(vz) * vz;
            s[j].w = __frsqrt_rn(vw) * vw;
            acc += (s[j].x + s[j].y) + (s[j].z + s[j].w);
        }
        acc += __shfl_xor_sync(0xffffffffu, acc, 16);
        acc += __shfl_xor_sync(0xffffffffu, acc, 8);
        acc += __shfl_xor_sync(0xffffffffu, acc, 4);
        acc += __shfl_xor_sync(0xffffffffu, acc, 2);
        acc += __shfl_xor_sync(0xffffffffu, acc, 1);

        // n_c = s_c / (sum/C + EPS*sqrt(D));  y = x*(1 + gamma*n) + beta
        const float inv = __fdividef(1.0f, fmaf(acc, 1.0f / C, cs.y));

        #pragma unroll
        for (int j = 0; j < 4; j++) {
            const float4 g4 = sg[lane + j * 32];
            const float4 b4 = sb[lane + j * 32];
            float4 o;
            o.x = fmaf(cur[j].x, fmaf(g4.x, s[j].x * inv, 1.0f), b4.x);
            o.y = fmaf(cur[j].y, fmaf(g4.y, s[j].y * inv, 1.0f), b4.y);
            o.z = fmaf(cur[j].z, fmaf(g4.z, s[j].z * inv, 1.0f), b4.z);
            o.w = fmaf(cur[j].w, fmaf(g4.w, s[j].w * inv, 1.0f), b4.w);
            yb[(size_t)t * C4 + lane + j * 32] = o;
        }
        #pragma unroll
        for (int j = 0; j < 4; j++) cur[j] = nxt[j];
    }
}

extern "C" void kernel_launch(void* const* d_in, const int* in_sizes, int n_in,
                              void* d_out, int out_size) {
    const float* x     = (const float*)d_in[0];
    const float* gamma = (const float*)d_in[1];
    const float* beta  = (const float*)d_in[2];
    float* y           = (float*)d_out;

    pass1_kernel<<<NTASK / WPB, 256>>>(x);
    pass2_kernel<<<(B * C + 255) / 256, 256>>>();
    pass3_kernel<<<NTASK / WPB, 256>>>(x, gamma, beta, y);
}